// round 4
// baseline (speedup 1.0000x reference)
#include <cuda_runtime.h>
#include <cuda_bf16.h>
#include <math.h>
#include <stdint.h>

#define E_TOTAL 65536     // B*N*K = 2*1024*32
#define W3OFF   768       // SPLIT_OFF
#define RPN     768       // SPLIT_SZ

typedef __nv_bfloat16 bf16;

// ---- device scratch (no runtime allocation allowed) ----
// weights, transposed + hi/lo split: layout [N][K]
__device__ bf16 g_W1h[256 * 32],  g_W1l[256 * 32];
__device__ bf16 g_W2h[256 * 256], g_W2l[256 * 256];
__device__ bf16 g_W3h[768 * 256], g_W3l[768 * 256];
// activations, hi/lo split: layout [E][256]
__device__ bf16 g_H1h[(size_t)E_TOTAL * 256], g_H1l[(size_t)E_TOTAL * 256];
__device__ bf16 g_H2h[(size_t)E_TOTAL * 256], g_H2l[(size_t)E_TOTAL * 256];
__device__ float g_RP[(size_t)E_TOTAL * RPN];

__device__ __forceinline__ float gelu_exact(float x) {
    return 0.5f * x * (1.0f + erff(x * 0.70710678118654752440f));
}

// ---------------------------------------------------------------------------
// asm helpers
// ---------------------------------------------------------------------------
#define CPA16(dst_u32, src_ptr) \
    asm volatile("cp.async.cg.shared.global [%0], [%1], 16;" :: "r"(dst_u32), "l"(src_ptr))
#define CPA_COMMIT() asm volatile("cp.async.commit_group;" ::: "memory")
#define CPA_WAIT(n)  asm volatile("cp.async.wait_group %0;" :: "n"(n) : "memory")

#define LDSM4(R, addr)                                                        \
    asm volatile("ldmatrix.sync.aligned.m8n8.x4.shared.b16 {%0,%1,%2,%3}, [%4];" \
                 : "=r"((R)[0]), "=r"((R)[1]), "=r"((R)[2]), "=r"((R)[3])     \
                 : "r"(addr))

__device__ __forceinline__ void mma_bf16(float* d, const uint32_t* a,
                                         uint32_t b0, uint32_t b1) {
    asm volatile(
        "mma.sync.aligned.m16n8k16.row.col.f32.bf16.bf16.f32 "
        "{%0,%1,%2,%3}, {%4,%5,%6,%7}, {%8,%9}, {%0,%1,%2,%3};"
        : "+f"(d[0]), "+f"(d[1]), "+f"(d[2]), "+f"(d[3])
        : "r"(a[0]), "r"(a[1]), "r"(a[2]), "r"(a[3]), "r"(b0), "r"(b1));
}

// smem swizzle: tile rows of 32 bf16 (4 chunks of 16B). conflict-free for
// both cp.async stores and ldmatrix phases.
__device__ __forceinline__ uint32_t swz(int row, int kc) {
    return (uint32_t)(row * 4 + (kc ^ ((row >> 1) & 3))) * 16u;
}

// ---------------------------------------------------------------------------
// prep: transpose + hi/lo split weights.  out[n*K + k] = split(W[k*ldw + coff + n])
// ---------------------------------------------------------------------------
__global__ void prep_weight(const float* __restrict__ W, int K, int N, int ldw,
                            int coff, bf16* __restrict__ hi, bf16* __restrict__ lo)
{
    int idx = blockIdx.x * 256 + threadIdx.x;
    if (idx >= K * N) return;
    int n = idx / K, k = idx - n * K;
    float v = W[(size_t)k * ldw + coff + n];
    bf16 h = __float2bfloat16_rn(v);
    hi[idx] = h;
    lo[idx] = __float2bfloat16_rn(v - __bfloat162float(h));
}

// ---------------------------------------------------------------------------
// Tensor-core GEMM: C[64 x 256-chunk] = act(A[E,KTOT] @ B) via split-bf16.
// BM=64, BN=256, BK=32. 8 warps (2m x 4n), warp tile 32x64.
// smem (dynamic, 80KB):
//   A: (buf*2 + h)*4096           (64 rows x 64B swizzled)
//   B: 16384 + (buf*2 + h)*16384  (256 rows x 64B swizzled)
// ---------------------------------------------------------------------------
template<int KTOT, bool GELU, bool ASPLIT>
__global__ __launch_bounds__(256, 2)
void mma_gemm(const float* __restrict__ Af,
              const bf16* __restrict__ Ah, const bf16* __restrict__ Al,
              const bf16* __restrict__ Bh, const bf16* __restrict__ Bl,
              const float* __restrict__ bias,
              float* __restrict__ Cf, bf16* __restrict__ Ch, bf16* __restrict__ Cl,
              int ldc)
{
    extern __shared__ __align__(16) char smem[];
    const uint32_t smem_u = (uint32_t)__cvta_generic_to_shared(smem);

    const int tid  = threadIdx.x;
    const int warp = tid >> 5, lane = tid & 31;
    const int wm = warp >> 2, wn = warp & 3;       // 2 x 4 warp grid
    const int row0 = blockIdx.x * 64;
    const int cb   = blockIdx.y;                   // 256-col chunk
    constexpr int NT = KTOT / 32;

    const int lrow = tid >> 2;    // A loader: 64 rows x 4 chunks
    const int lkc  = tid & 3;

    float acc[2][8][4];
#pragma unroll
    for (int i = 0; i < 2; i++)
#pragma unroll
        for (int j = 0; j < 8; j++)
#pragma unroll
            for (int q = 0; q < 4; q++) acc[i][j][q] = 0.f;

    // ---- tile issue ----
    auto issue = [&](int buf, int kt) {
        // A
        if (ASPLIT) {
            const bf16* sh = Ah + (size_t)(row0 + lrow) * KTOT + kt * 32 + lkc * 8;
            const bf16* sl = Al + (size_t)(row0 + lrow) * KTOT + kt * 32 + lkc * 8;
            uint32_t d = smem_u + buf * 8192 + swz(lrow, lkc);
            CPA16(d, sh);
            CPA16(d + 4096, sl);
        } else {
            // fp32 A, runtime split (only KTOT=32 path, NT=1)
            const float* src = Af + (size_t)(row0 + lrow) * KTOT + kt * 32 + lkc * 8;
            float4 v0 = *(const float4*)(src);
            float4 v1 = *(const float4*)(src + 4);
            float f[8] = {v0.x, v0.y, v0.z, v0.w, v1.x, v1.y, v1.z, v1.w};
            __nv_bfloat162 hh[4], ll[4];
#pragma unroll
            for (int i = 0; i < 4; i++) {
                bf16 h0 = __float2bfloat16_rn(f[2*i]);
                bf16 h1 = __float2bfloat16_rn(f[2*i+1]);
                hh[i].x = h0; hh[i].y = h1;
                ll[i].x = __float2bfloat16_rn(f[2*i]   - __bfloat162float(h0));
                ll[i].y = __float2bfloat16_rn(f[2*i+1] - __bfloat162float(h1));
            }
            uint32_t off = buf * 8192 + swz(lrow, lkc);
            *(uint4*)(smem + off)        = *(uint4*)hh;
            *(uint4*)(smem + off + 4096) = *(uint4*)ll;
        }
        // B: 1024 chunks per h, 4 per thread
#pragma unroll
        for (int i = 0; i < 4; i++) {
            int idx = tid + i * 256;
            int nl  = idx >> 2, kc = idx & 3;
            const bf16* sh = Bh + (size_t)(cb * 256 + nl) * KTOT + kt * 32 + kc * 8;
            const bf16* sl = Bl + (size_t)(cb * 256 + nl) * KTOT + kt * 32 + kc * 8;
            uint32_t d = smem_u + 16384 + buf * 32768 + swz(nl, kc);
            CPA16(d, sh);
            CPA16(d + 16384, sl);
        }
    };

    issue(0, 0);
    CPA_COMMIT();

    int buf = 0;
#pragma unroll 1
    for (int kt = 0; kt < NT; kt++) {
        if (kt + 1 < NT) {
            issue(buf ^ 1, kt + 1);
            CPA_COMMIT();
            CPA_WAIT(1);
        } else {
            CPA_WAIT(0);
        }
        __syncthreads();

        const uint32_t aB = smem_u + buf * 8192;
        const uint32_t bB = smem_u + 16384 + buf * 32768;
        const int sel = lane >> 3;
        const int lr8 = lane & 7;

#pragma unroll
        for (int ks = 0; ks < 2; ks++) {
            const int kc = ks * 2 + (sel >> 1);
            uint32_t ahr[2][4], alr[2][4];
#pragma unroll
            for (int mi = 0; mi < 2; mi++) {
                int rl = wm * 32 + mi * 16 + (sel & 1) * 8 + lr8;
                uint32_t ad = aB + swz(rl, kc);
                LDSM4(ahr[mi], ad);
                LDSM4(alr[mi], ad + 4096);
            }
#pragma unroll
            for (int nj16 = 0; nj16 < 4; nj16++) {
                int rl = wn * 64 + nj16 * 16 + (sel & 1) * 8 + lr8;
                uint32_t bd = bB + swz(rl, kc);
                uint32_t bhr[4], blr[4];
                LDSM4(bhr, bd);
                LDSM4(blr, bd + 16384);
#pragma unroll
                for (int mi = 0; mi < 2; mi++) {
                    float* ae = acc[mi][nj16 * 2];
                    float* ao = acc[mi][nj16 * 2 + 1];
                    mma_bf16(ae, ahr[mi], bhr[0], bhr[2]);   // hi*hi
                    mma_bf16(ae, ahr[mi], blr[0], blr[2]);   // hi*lo
                    mma_bf16(ae, alr[mi], bhr[0], bhr[2]);   // lo*hi
                    mma_bf16(ao, ahr[mi], bhr[1], bhr[3]);
                    mma_bf16(ao, ahr[mi], blr[1], blr[3]);
                    mma_bf16(ao, alr[mi], bhr[1], bhr[3]);
                }
            }
        }
        __syncthreads();
        buf ^= 1;
    }

    // ---- epilogue ----
    const int r = lane >> 2, c = lane & 3;
#pragma unroll
    for (int mi = 0; mi < 2; mi++) {
#pragma unroll
        for (int nj = 0; nj < 8; nj++) {
            int row = row0 + wm * 32 + mi * 16 + r;
            int col = cb * 256 + wn * 64 + nj * 8 + c * 2;
            float b0 = bias ? bias[col]     : 0.f;
            float b1 = bias ? bias[col + 1] : 0.f;
            float x0 = acc[mi][nj][0] + b0;
            float x1 = acc[mi][nj][1] + b1;
            float x2 = acc[mi][nj][2] + b0;
            float x3 = acc[mi][nj][3] + b1;
            if (GELU) {
                x0 = gelu_exact(x0); x1 = gelu_exact(x1);
                x2 = gelu_exact(x2); x3 = gelu_exact(x3);
                // write split bf16 activations (ldc == 256)
                size_t o0 = (size_t)row * 256 + col;
                size_t o1 = (size_t)(row + 8) * 256 + col;
                __nv_bfloat162 h0, h1, l0, l1;
                h0.x = __float2bfloat16_rn(x0);
                h0.y = __float2bfloat16_rn(x1);
                l0.x = __float2bfloat16_rn(x0 - __bfloat162float(h0.x));
                l0.y = __float2bfloat16_rn(x1 - __bfloat162float(h0.y));
                h1.x = __float2bfloat16_rn(x2);
                h1.y = __float2bfloat16_rn(x3);
                l1.x = __float2bfloat16_rn(x2 - __bfloat162float(h1.x));
                l1.y = __float2bfloat16_rn(x3 - __bfloat162float(h1.y));
                *(__nv_bfloat162*)&Ch[o0] = h0;
                *(__nv_bfloat162*)&Cl[o0] = l0;
                *(__nv_bfloat162*)&Ch[o1] = h1;
                *(__nv_bfloat162*)&Cl[o1] = l1;
            } else {
                *(float2*)&Cf[(size_t)row * ldc + col]       = make_float2(x0, x1);
                *(float2*)&Cf[(size_t)(row + 8) * ldc + col] = make_float2(x2, x3);
            }
        }
    }
}

// ---------------------------------------------------------------------------
// Tail: per edge e,
//   tmp[j=i*3+n][dd] = sum_d f[i,d] * basis[d, n*3+dd]       (48 x 3)
//   out[o][dd]       = sum_j RP[e, o*48 + j] * tmp[j][dd]    (16 x 3)
// ---------------------------------------------------------------------------
__global__ __launch_bounds__(256)
void tail_kernel(const float* __restrict__ RP, const float* __restrict__ feats,
                 const float* __restrict__ basis, float* __restrict__ out)
{
    __shared__ float sT[16][145];
    __shared__ float sF[16][48];
    __shared__ float sBA[16][27];

    const int tid = threadIdx.x;
    const int el  = tid >> 4;
    const int o   = tid & 15;
    const size_t e = (size_t)blockIdx.x * 16 + el;

    const float* fe = feats + e * 48;
    sF[el][o*3+0] = fe[o*3+0];
    sF[el][o*3+1] = fe[o*3+1];
    sF[el][o*3+2] = fe[o*3+2];
    const float* be = basis + e * 27;
    for (int idx = o; idx < 27; idx += 16) sBA[el][idx] = be[idx];
    __syncthreads();

#pragma unroll
    for (int jj = 0; jj < 3; jj++) {
        int j = o + jj * 16;
        int i = j / 3, n = j - i * 3;
        float f0 = sF[el][i*3+0], f1 = sF[el][i*3+1], f2 = sF[el][i*3+2];
#pragma unroll
        for (int dd = 0; dd < 3; dd++) {
            sT[el][j*3 + dd] = f0 * sBA[el][n*3 + dd]
                             + f1 * sBA[el][9 + n*3 + dd]
                             + f2 * sBA[el][18 + n*3 + dd];
        }
    }
    __syncthreads();

    const float4* rp4 = (const float4*)(RP + e * RPN + o * 48);
    float s0 = 0.f, s1 = 0.f, s2 = 0.f;
    const float* tp = sT[el];
#pragma unroll
    for (int q = 0; q < 12; q++) {
        float4 rv = rp4[q];
        int j = q * 4;
        s0 = fmaf(rv.x, tp[(j+0)*3+0], s0);
        s1 = fmaf(rv.x, tp[(j+0)*3+1], s1);
        s2 = fmaf(rv.x, tp[(j+0)*3+2], s2);
        s0 = fmaf(rv.y, tp[(j+1)*3+0], s0);
        s1 = fmaf(rv.y, tp[(j+1)*3+1], s1);
        s2 = fmaf(rv.y, tp[(j+1)*3+2], s2);
        s0 = fmaf(rv.z, tp[(j+2)*3+0], s0);
        s1 = fmaf(rv.z, tp[(j+2)*3+1], s1);
        s2 = fmaf(rv.z, tp[(j+2)*3+2], s2);
        s0 = fmaf(rv.w, tp[(j+3)*3+0], s0);
        s1 = fmaf(rv.w, tp[(j+3)*3+1], s1);
        s2 = fmaf(rv.w, tp[(j+3)*3+2], s2);
    }
    float* op = out + (e * 16 + o) * 3;
    op[0] = s0; op[1] = s1; op[2] = s2;
}

// ---------------------------------------------------------------------------
extern "C" void kernel_launch(void* const* d_in, const int* in_sizes, int n_in,
                              void* d_out, int out_size)
{
    const float* edges = (const float*)d_in[0];
    const float* feats = (const float*)d_in[1];
    const float* basis = (const float*)d_in[2];
    const float* W1    = (const float*)d_in[3];
    const float* b1    = (const float*)d_in[4];
    const float* W2    = (const float*)d_in[5];
    const float* b2    = (const float*)d_in[6];
    const float* W3    = (const float*)d_in[7];
    float* out = (float*)d_out;

    bf16 *W1h, *W1l, *W2h, *W2l, *W3h, *W3l, *H1h, *H1l, *H2h, *H2l;
    float *RP;
    cudaGetSymbolAddress((void**)&W1h, g_W1h);
    cudaGetSymbolAddress((void**)&W1l, g_W1l);
    cudaGetSymbolAddress((void**)&W2h, g_W2h);
    cudaGetSymbolAddress((void**)&W2l, g_W2l);
    cudaGetSymbolAddress((void**)&W3h, g_W3h);
    cudaGetSymbolAddress((void**)&W3l, g_W3l);
    cudaGetSymbolAddress((void**)&H1h, g_H1h);
    cudaGetSymbolAddress((void**)&H1l, g_H1l);
    cudaGetSymbolAddress((void**)&H2h, g_H2h);
    cudaGetSymbolAddress((void**)&H2l, g_H2l);
    cudaGetSymbolAddress((void**)&RP,  g_RP);

    const int SMEM = 81920;
    cudaFuncSetAttribute(mma_gemm<32,  true,  false>,
                         cudaFuncAttributeMaxDynamicSharedMemorySize, SMEM);
    cudaFuncSetAttribute(mma_gemm<256, true,  true>,
                         cudaFuncAttributeMaxDynamicSharedMemorySize, SMEM);
    cudaFuncSetAttribute(mma_gemm<256, false, true>,
                         cudaFuncAttributeMaxDynamicSharedMemorySize, SMEM);

    // weight prep (transpose + split)
    prep_weight<<<(32 * 256 + 255) / 256, 256>>>(W1, 32, 256, 256, 0, W1h, W1l);
    prep_weight<<<(256 * 256 + 255) / 256, 256>>>(W2, 256, 256, 256, 0, W2h, W2l);
    prep_weight<<<(256 * 768 + 255) / 256, 256>>>(W3, 256, 768, 1536, W3OFF, W3h, W3l);

    dim3 blk(256);
    // layer 1: gelu(edges @ W1 + b1) -> H1 split
    mma_gemm<32, true, false><<<dim3(E_TOTAL / 64, 1), blk, SMEM>>>(
        edges, nullptr, nullptr, W1h, W1l, b1, nullptr, H1h, H1l, 256);
    // layer 2: gelu(H1 @ W2 + b2) -> H2 split
    mma_gemm<256, true, true><<<dim3(E_TOTAL / 64, 1), blk, SMEM>>>(
        nullptr, H1h, H1l, W2h, W2l, b2, nullptr, H2h, H2l, 256);
    // layer 3: H2 @ W3[:,768:1536] -> RP fp32 (768 cols = 3 chunks)
    mma_gemm<256, false, true><<<dim3(E_TOTAL / 64, 3), blk, SMEM>>>(
        nullptr, H2h, H2l, W3h, W3l, nullptr, RP, nullptr, nullptr, RPN);
    // tail
    tail_kernel<<<E_TOTAL / 16, blk>>>(RP, feats, basis, out);
}

// round 6
// speedup vs baseline: 2.0396x; 2.0396x over previous
#include <cuda_runtime.h>
#include <cuda_fp16.h>
#include <math.h>
#include <stdint.h>

#define E_TOTAL 65536     // B*N*K
#define W3OFF   768       // SPLIT_OFF
#define RPN     768       // SPLIT_SZ

// ---- device scratch ----
// weights transposed [N][K], fp16 hi/lo split
__device__ __half g_W1h[256 * 32],  g_W1l[256 * 32];
__device__ __half g_W2h[256 * 256], g_W2l[256 * 256];
__device__ __half g_W3h[768 * 256], g_W3l[768 * 256];
// activations [E][256] plain fp16
__device__ __half g_H1[(size_t)E_TOTAL * 256];
__device__ __half g_H2[(size_t)E_TOTAL * 256];
__device__ float  g_RP[(size_t)E_TOTAL * RPN];

__device__ __forceinline__ float gelu_exact(float x) {
    return 0.5f * x * (1.0f + erff(x * 0.70710678118654752440f));
}

// ---------------------------------------------------------------------------
#define CPA16(dst_u32, src_ptr) \
    asm volatile("cp.async.cg.shared.global [%0], [%1], 16;" :: "r"(dst_u32), "l"(src_ptr))
#define CPA_COMMIT() asm volatile("cp.async.commit_group;" ::: "memory")
#define CPA_WAIT(n)  asm volatile("cp.async.wait_group %0;" :: "n"(n) : "memory")

#define LDSM4(R, addr)                                                        \
    asm volatile("ldmatrix.sync.aligned.m8n8.x4.shared.b16 {%0,%1,%2,%3}, [%4];" \
                 : "=r"((R)[0]), "=r"((R)[1]), "=r"((R)[2]), "=r"((R)[3])     \
                 : "r"(addr))

__device__ __forceinline__ void mma_f16(float* d, const uint32_t* a,
                                        uint32_t b0, uint32_t b1) {
    asm volatile(
        "mma.sync.aligned.m16n8k16.row.col.f32.f16.f16.f32 "
        "{%0,%1,%2,%3}, {%4,%5,%6,%7}, {%8,%9}, {%0,%1,%2,%3};"
        : "+f"(d[0]), "+f"(d[1]), "+f"(d[2]), "+f"(d[3])
        : "r"(a[0]), "r"(a[1]), "r"(a[2]), "r"(a[3]), "r"(b0), "r"(b1));
}

// swizzled byte offset for 64B rows (4 chunks of 16B); conflict-free for
// cp.async stores AND ldmatrix phases (validated numerically in R4).
__device__ __forceinline__ uint32_t soff(int r, int c) {
    return (uint32_t)((r * 4 + (c ^ ((r >> 1) & 3))) << 4);
}

// ---------------------------------------------------------------------------
// prep: transpose + fp16 hi/lo split weights. out[n*K+k] = split(W[k*ldw+coff+n])
// ---------------------------------------------------------------------------
__global__ void prep_weight(const float* __restrict__ W, int K, int N, int ldw,
                            int coff, __half* __restrict__ hi, __half* __restrict__ lo)
{
    int idx = blockIdx.x * 256 + threadIdx.x;
    if (idx >= N * K) return;
    int n = idx / K, k = idx - n * K;
    float v = W[(size_t)k * ldw + coff + n];
    __half h = __float2half_rn(v);
    hi[idx] = h;
    lo[idx] = __float2half_rn(v - __half2float(h));
}

// ---------------------------------------------------------------------------
// fp16 HMMA GEMM, weights hi/lo split (2 passes):
//   C[128 x 128-chunk] = act( A[E,K] @ (Wh+Wl) (+bias) )
// BM=128 BN=128 BK=32, 3-stage cp.async pipeline, 8 warps (2m x 4n), warp 64x32.
// smem stage (24576B): A @0 (8K), Bh @8192 (8K), Bl @16384 (8K)
// ---------------------------------------------------------------------------
#define STAGE_SZ 24576
#define SMEM_SZ  (3 * STAGE_SZ)

template<int NT, bool GELU, bool AFP32>
__global__ __launch_bounds__(256, 2)
void hgemm(const float* __restrict__ Af, const __half* __restrict__ Ain, int lda,
           const __half* __restrict__ Bh, const __half* __restrict__ Bl, int ldb,
           const float* __restrict__ bias,
           float* __restrict__ Cf, __half* __restrict__ Ch, int ldc)
{
    extern __shared__ __align__(128) char smem_c[];
    const uint32_t smem_u = (uint32_t)__cvta_generic_to_shared(smem_c);

    const int tid  = threadIdx.x;
    const int wid  = tid >> 5;
    const int lane = tid & 31;
    const int wm   = wid >> 2;      // 0..1
    const int wn   = wid & 3;       // 0..3
    const int row0 = blockIdx.x * 128;
    const int cb   = blockIdx.y;

    float acc[4][4][4];
#pragma unroll
    for (int i = 0; i < 4; i++)
#pragma unroll
        for (int j = 0; j < 4; j++)
#pragma unroll
            for (int q = 0; q < 4; q++) acc[i][j][q] = 0.f;

    // loader indices: 512 16B-chunks per tile, 2 per thread
    const int lr0 = tid >> 2, lc0 = tid & 3;          // chunk 0: idx=tid
    const int lr1 = (tid + 256) >> 2, lc1 = lc0;      // chunk 1: idx=tid+256

    auto load_tile = [&](int s, int kt) {
        const uint32_t base = smem_u + s * STAGE_SZ;
        if constexpr (!AFP32) {
            CPA16(base + soff(lr0, lc0),
                  Ain + (size_t)(row0 + lr0) * lda + kt * 32 + lc0 * 8);
            CPA16(base + soff(lr1, lc1),
                  Ain + (size_t)(row0 + lr1) * lda + kt * 32 + lc1 * 8);
        }
        const __half* bh0 = Bh + (size_t)(cb * 128 + lr0) * ldb + kt * 32 + lc0 * 8;
        const __half* bh1 = Bh + (size_t)(cb * 128 + lr1) * ldb + kt * 32 + lc1 * 8;
        const __half* bl0 = Bl + (size_t)(cb * 128 + lr0) * ldb + kt * 32 + lc0 * 8;
        const __half* bl1 = Bl + (size_t)(cb * 128 + lr1) * ldb + kt * 32 + lc1 * 8;
        CPA16(base + 8192  + soff(lr0, lc0), bh0);
        CPA16(base + 8192  + soff(lr1, lc1), bh1);
        CPA16(base + 16384 + soff(lr0, lc0), bl0);
        CPA16(base + 16384 + soff(lr1, lc1), bl1);
    };

    if constexpr (AFP32) {
        // fp32 A (K=32, single tile): convert to fp16 into stage 0
        int r = tid >> 1, hf = tid & 1;
        const float4* s4 = (const float4*)(Af + (size_t)(row0 + r) * lda + hf * 16);
        __half2 hx[8];
#pragma unroll
        for (int q = 0; q < 4; q++) {
            float4 v = s4[q];
            hx[2*q]   = __float22half2_rn(make_float2(v.x, v.y));
            hx[2*q+1] = __float22half2_rn(make_float2(v.z, v.w));
        }
        *(uint4*)(smem_c + soff(r, hf * 2))     = *(uint4*)&hx[0];
        *(uint4*)(smem_c + soff(r, hf * 2 + 1)) = *(uint4*)&hx[4];
        load_tile(0, 0);   // B only
        CPA_COMMIT();
    } else {
        load_tile(0, 0);
        CPA_COMMIT();
        if (NT > 1) { load_tile(1, 1); CPA_COMMIT(); }
    }

    // per-lane ldmatrix address components
    const int lr  = (lane & 7) | (((lane >> 3) & 1) << 3);
    const int lkc = lane >> 4;

#pragma unroll 1
    for (int kt = 0; kt < NT; kt++) {
        if (kt + 1 < NT) { CPA_WAIT(1); } else { CPA_WAIT(0); }
        __syncthreads();

        const uint32_t base = smem_u + (kt % 3) * STAGE_SZ;
        uint32_t aA[4], bhA[2], blA[2];
#pragma unroll
        for (int mi = 0; mi < 4; mi++)
            aA[mi] = base + soff(wm * 64 + mi * 16 + lr, lkc);
#pragma unroll
        for (int ng = 0; ng < 2; ng++) {
            int rb = wn * 32 + ng * 16 + lr;
            bhA[ng] = base + 8192  + soff(rb, lkc);
            blA[ng] = base + 16384 + soff(rb, lkc);
        }

#pragma unroll
        for (int ks = 0; ks < 2; ks++) {
            const uint32_t xo = ks * 32;    // k16 step flips bit1 of chunk idx
            uint32_t ar[4][4];
#pragma unroll
            for (int mi = 0; mi < 4; mi++) LDSM4(ar[mi], aA[mi] ^ xo);
#pragma unroll
            for (int ng = 0; ng < 2; ng++) {
                uint32_t bh4[4], bl4[4];
                LDSM4(bh4, bhA[ng] ^ xo);
                LDSM4(bl4, blA[ng] ^ xo);
#pragma unroll
                for (int mi = 0; mi < 4; mi++) {
                    mma_f16(acc[mi][ng*2],   ar[mi], bh4[0], bh4[2]);
                    mma_f16(acc[mi][ng*2],   ar[mi], bl4[0], bl4[2]);
                    mma_f16(acc[mi][ng*2+1], ar[mi], bh4[1], bh4[3]);
                    mma_f16(acc[mi][ng*2+1], ar[mi], bl4[1], bl4[3]);
                }
            }
        }

        if (kt + 2 < NT) {
            load_tile((kt + 2) % 3, kt + 2);
            CPA_COMMIT();
        }
    }

    // ---- epilogue (direct fragment stores) ----
    const int r = lane >> 2, c2 = lane & 3;
#pragma unroll
    for (int mi = 0; mi < 4; mi++) {
#pragma unroll
        for (int nj = 0; nj < 4; nj++) {
            int row = row0 + wm * 64 + mi * 16 + r;
            int col = cb * 128 + wn * 32 + nj * 8 + c2 * 2;
            float b0 = 0.f, b1 = 0.f;
            if (GELU) { b0 = bias[col]; b1 = bias[col + 1]; }
            float x0 = acc[mi][nj][0] + b0;
            float x1 = acc[mi][nj][1] + b1;
            float x2 = acc[mi][nj][2] + b0;
            float x3 = acc[mi][nj][3] + b1;
            if constexpr (GELU) {
                x0 = gelu_exact(x0); x1 = gelu_exact(x1);
                x2 = gelu_exact(x2); x3 = gelu_exact(x3);
                *(__half2*)&Ch[(size_t)row * ldc + col] =
                    __float22half2_rn(make_float2(x0, x1));
                *(__half2*)&Ch[(size_t)(row + 8) * ldc + col] =
                    __float22half2_rn(make_float2(x2, x3));
            } else {
                *(float2*)&Cf[(size_t)row * ldc + col]       = make_float2(x0, x1);
                *(float2*)&Cf[(size_t)(row + 8) * ldc + col] = make_float2(x2, x3);
            }
        }
    }
}

// ---------------------------------------------------------------------------
// Tail: per edge e,
//   tmp[j=i*3+n][dd] = sum_d f[i,d] * basis[d, n*3+dd]       (48 x 3)
//   out[o][dd]       = sum_j RP[e, o*48 + j] * tmp[j][dd]    (16 x 3)
// ---------------------------------------------------------------------------
__global__ __launch_bounds__(256)
void tail_kernel(const float* __restrict__ RP, const float* __restrict__ feats,
                 const float* __restrict__ basis, float* __restrict__ out)
{
    __shared__ float sT[16][145];
    __shared__ float sF[16][48];
    __shared__ float sBA[16][27];

    const int tid = threadIdx.x;
    const int el  = tid >> 4;
    const int o   = tid & 15;
    const size_t e = (size_t)blockIdx.x * 16 + el;

    const float* fe = feats + e * 48;
    sF[el][o*3+0] = fe[o*3+0];
    sF[el][o*3+1] = fe[o*3+1];
    sF[el][o*3+2] = fe[o*3+2];
    const float* be = basis + e * 27;
    for (int idx = o; idx < 27; idx += 16) sBA[el][idx] = be[idx];
    __syncthreads();

#pragma unroll
    for (int jj = 0; jj < 3; jj++) {
        int j = o + jj * 16;
        int i = j / 3, n = j - i * 3;
        float f0 = sF[el][i*3+0], f1 = sF[el][i*3+1], f2 = sF[el][i*3+2];
#pragma unroll
        for (int dd = 0; dd < 3; dd++) {
            sT[el][j*3 + dd] = f0 * sBA[el][n*3 + dd]
                             + f1 * sBA[el][9 + n*3 + dd]
                             + f2 * sBA[el][18 + n*3 + dd];
        }
    }
    __syncthreads();

    const float4* rp4 = (const float4*)(RP + e * RPN + o * 48);
    float s0 = 0.f, s1 = 0.f, s2 = 0.f;
    const float* tp = sT[el];
#pragma unroll
    for (int q = 0; q < 12; q++) {
        float4 rv = rp4[q];
        int j = q * 4;
        s0 = fmaf(rv.x, tp[(j+0)*3+0], s0);
        s1 = fmaf(rv.x, tp[(j+0)*3+1], s1);
        s2 = fmaf(rv.x, tp[(j+0)*3+2], s2);
        s0 = fmaf(rv.y, tp[(j+1)*3+0], s0);
        s1 = fmaf(rv.y, tp[(j+1)*3+1], s1);
        s2 = fmaf(rv.y, tp[(j+1)*3+2], s2);
        s0 = fmaf(rv.z, tp[(j+2)*3+0], s0);
        s1 = fmaf(rv.z, tp[(j+2)*3+1], s1);
        s2 = fmaf(rv.z, tp[(j+2)*3+2], s2);
        s0 = fmaf(rv.w, tp[(j+3)*3+0], s0);
        s1 = fmaf(rv.w, tp[(j+3)*3+1], s1);
        s2 = fmaf(rv.w, tp[(j+3)*3+2], s2);
    }
    float* op = out + (e * 16 + o) * 3;
    op[0] = s0; op[1] = s1; op[2] = s2;
}

// ---------------------------------------------------------------------------
extern "C" void kernel_launch(void* const* d_in, const int* in_sizes, int n_in,
                              void* d_out, int out_size)
{
    const float* edges = (const float*)d_in[0];
    const float* feats = (const float*)d_in[1];
    const float* basis = (const float*)d_in[2];
    const float* W1    = (const float*)d_in[3];
    const float* b1    = (const float*)d_in[4];
    const float* W2    = (const float*)d_in[5];
    const float* b2    = (const float*)d_in[6];
    const float* W3    = (const float*)d_in[7];
    float* out = (float*)d_out;

    __half *W1h, *W1l, *W2h, *W2l, *W3h, *W3l, *H1, *H2;
    float *RP;
    cudaGetSymbolAddress((void**)&W1h, g_W1h);
    cudaGetSymbolAddress((void**)&W1l, g_W1l);
    cudaGetSymbolAddress((void**)&W2h, g_W2h);
    cudaGetSymbolAddress((void**)&W2l, g_W2l);
    cudaGetSymbolAddress((void**)&W3h, g_W3h);
    cudaGetSymbolAddress((void**)&W3l, g_W3l);
    cudaGetSymbolAddress((void**)&H1,  g_H1);
    cudaGetSymbolAddress((void**)&H2,  g_H2);
    cudaGetSymbolAddress((void**)&RP,  g_RP);

    cudaFuncSetAttribute(hgemm<1, true,  true>,
                         cudaFuncAttributeMaxDynamicSharedMemorySize, SMEM_SZ);
    cudaFuncSetAttribute(hgemm<8, true,  false>,
                         cudaFuncAttributeMaxDynamicSharedMemorySize, SMEM_SZ);
    cudaFuncSetAttribute(hgemm<8, false, false>,
                         cudaFuncAttributeMaxDynamicSharedMemorySize, SMEM_SZ);

    // weight prep (transpose + fp16 hi/lo split)
    prep_weight<<<(256 * 32 + 255) / 256, 256>>>(W1, 32, 256, 256, 0, W1h, W1l);
    prep_weight<<<(256 * 256 + 255) / 256, 256>>>(W2, 256, 256, 256, 0, W2h, W2l);
    prep_weight<<<(768 * 256 + 255) / 256, 256>>>(W3, 256, 768, 1536, W3OFF, W3h, W3l);

    dim3 blk(256);
    // layer 1: gelu(edges @ W1 + b1) -> H1 fp16  (256 cols = 2 chunks of 128)
    hgemm<1, true, true><<<dim3(E_TOTAL / 128, 2), blk, SMEM_SZ>>>(
        edges, nullptr, 32, W1h, W1l, 32, b1, nullptr, H1, 256);
    // layer 2: gelu(H1 @ W2 + b2) -> H2 fp16
    hgemm<8, true, false><<<dim3(E_TOTAL / 128, 2), blk, SMEM_SZ>>>(
        nullptr, H1, 256, W2h, W2l, 256, b2, nullptr, H2, 256);
    // layer 3: H2 @ W3[:,768:1536] -> RP fp32  (768 cols = 6 chunks of 128)
    hgemm<8, false, false><<<dim3(E_TOTAL / 128, 6), blk, SMEM_SZ>>>(
        nullptr, H2, 256, W3h, W3l, 256, nullptr, RP, nullptr, RPN);
    // tail
    tail_kernel<<<E_TOTAL / 16, blk>>>(RP, feats, basis, out);
}

// round 7
// speedup vs baseline: 2.6054x; 1.2774x over previous
#include <cuda_runtime.h>
#include <cuda_fp16.h>
#include <math.h>
#include <stdint.h>

#define E_TOTAL 65536     // B*N*K
#define W3OFF   768       // SPLIT_OFF
#define RPN     768       // SPLIT_SZ

// ---- device scratch ----
// weights transposed [N][K], fp16 (hi, + lo only used for W1)
__device__ __half g_W1h[256 * 32],  g_W1l[256 * 32];
__device__ __half g_W2h[256 * 256];
__device__ __half g_W3h[768 * 256];
// activations [E][256] plain fp16
__device__ __half g_H1[(size_t)E_TOTAL * 256];
__device__ __half g_H2[(size_t)E_TOTAL * 256];
__device__ float  g_RP[(size_t)E_TOTAL * RPN];

__device__ __forceinline__ float gelu_exact(float x) {
    return 0.5f * x * (1.0f + erff(x * 0.70710678118654752440f));
}

// ---------------------------------------------------------------------------
#define CPA16(dst_u32, src_ptr) \
    asm volatile("cp.async.cg.shared.global [%0], [%1], 16;" :: "r"(dst_u32), "l"(src_ptr))
#define CPA_COMMIT() asm volatile("cp.async.commit_group;" ::: "memory")
#define CPA_WAIT(n)  asm volatile("cp.async.wait_group %0;" :: "n"(n) : "memory")

#define LDSM4(R, addr)                                                        \
    asm volatile("ldmatrix.sync.aligned.m8n8.x4.shared.b16 {%0,%1,%2,%3}, [%4];" \
                 : "=r"((R)[0]), "=r"((R)[1]), "=r"((R)[2]), "=r"((R)[3])     \
                 : "r"(addr))

__device__ __forceinline__ void mma_f16(float* d, const uint32_t* a,
                                        uint32_t b0, uint32_t b1) {
    asm volatile(
        "mma.sync.aligned.m16n8k16.row.col.f32.f16.f16.f32 "
        "{%0,%1,%2,%3}, {%4,%5,%6,%7}, {%8,%9}, {%0,%1,%2,%3};"
        : "+f"(d[0]), "+f"(d[1]), "+f"(d[2]), "+f"(d[3])
        : "r"(a[0]), "r"(a[1]), "r"(a[2]), "r"(a[3]), "r"(b0), "r"(b1));
}

// swizzled byte offset for 64B rows (4 chunks of 16B); conflict-free for
// cp.async stores AND ldmatrix phases (validated in R4/R6).
__device__ __forceinline__ uint32_t soff(int r, int c) {
    return (uint32_t)((r * 4 + (c ^ ((r >> 1) & 3))) << 4);
}

// ---------------------------------------------------------------------------
// prep: transpose + fp16 hi(/lo) split weights. out[n*K+k] from W[k*ldw+coff+n]
// ---------------------------------------------------------------------------
__global__ void prep_weight(const float* __restrict__ W, int K, int N, int ldw,
                            int coff, __half* __restrict__ hi, __half* __restrict__ lo)
{
    int idx = blockIdx.x * 256 + threadIdx.x;
    if (idx >= N * K) return;
    int n = idx / K, k = idx - n * K;
    float v = W[(size_t)k * ldw + coff + n];
    __half h = __float2half_rn(v);
    hi[idx] = h;
    if (lo) lo[idx] = __float2half_rn(v - __half2float(h));
}

// ---------------------------------------------------------------------------
// fp16 HMMA GEMM. BLO: add weight-lo pass (2-pass exact weights).
// BM=128 BN=128 BK=32, 3-stage cp.async pipeline, 8 warps (2m x 4n), warp 64x32.
// smem stage (24576B): A @0 (8K), Bh @8192 (8K), Bl @16384 (8K, only if BLO)
// ---------------------------------------------------------------------------
#define STAGE_SZ 24576
#define SMEM_SZ  (3 * STAGE_SZ)

template<int NT, bool GELU, bool AFP32, bool BLO>
__global__ __launch_bounds__(256, 2)
void hgemm(const float* __restrict__ Af, const __half* __restrict__ Ain, int lda,
           const __half* __restrict__ Bh, const __half* __restrict__ Bl, int ldb,
           const float* __restrict__ bias,
           float* __restrict__ Cf, __half* __restrict__ Ch, int ldc)
{
    extern __shared__ __align__(128) char smem_c[];
    const uint32_t smem_u = (uint32_t)__cvta_generic_to_shared(smem_c);

    const int tid  = threadIdx.x;
    const int wid  = tid >> 5;
    const int lane = tid & 31;
    const int wm   = wid >> 2;      // 0..1
    const int wn   = wid & 3;       // 0..3
    const int row0 = blockIdx.x * 128;
    const int cb   = blockIdx.y;

    float acc[4][4][4];
#pragma unroll
    for (int i = 0; i < 4; i++)
#pragma unroll
        for (int j = 0; j < 4; j++)
#pragma unroll
            for (int q = 0; q < 4; q++) acc[i][j][q] = 0.f;

    // loader indices: 512 16B-chunks per 128x32 tile, 2 per thread
    const int lr0 = tid >> 2, lc0 = tid & 3;
    const int lr1 = (tid + 256) >> 2, lc1 = lc0;

    auto load_tile = [&](int s, int kt) {
        const uint32_t base = smem_u + s * STAGE_SZ;
        if constexpr (!AFP32) {
            CPA16(base + soff(lr0, lc0),
                  Ain + (size_t)(row0 + lr0) * lda + kt * 32 + lc0 * 8);
            CPA16(base + soff(lr1, lc1),
                  Ain + (size_t)(row0 + lr1) * lda + kt * 32 + lc1 * 8);
        }
        CPA16(base + 8192 + soff(lr0, lc0),
              Bh + (size_t)(cb * 128 + lr0) * ldb + kt * 32 + lc0 * 8);
        CPA16(base + 8192 + soff(lr1, lc1),
              Bh + (size_t)(cb * 128 + lr1) * ldb + kt * 32 + lc1 * 8);
        if constexpr (BLO) {
            CPA16(base + 16384 + soff(lr0, lc0),
                  Bl + (size_t)(cb * 128 + lr0) * ldb + kt * 32 + lc0 * 8);
            CPA16(base + 16384 + soff(lr1, lc1),
                  Bl + (size_t)(cb * 128 + lr1) * ldb + kt * 32 + lc1 * 8);
        }
    };

    if constexpr (AFP32) {
        // fp32 A (K=32, single tile): convert to fp16 into stage 0
        int r = tid >> 1, hf = tid & 1;
        const float4* s4 = (const float4*)(Af + (size_t)(row0 + r) * lda + hf * 16);
        __half2 hx[8];
#pragma unroll
        for (int q = 0; q < 4; q++) {
            float4 v = s4[q];
            hx[2*q]   = __float22half2_rn(make_float2(v.x, v.y));
            hx[2*q+1] = __float22half2_rn(make_float2(v.z, v.w));
        }
        *(uint4*)(smem_c + soff(r, hf * 2))     = *(uint4*)&hx[0];
        *(uint4*)(smem_c + soff(r, hf * 2 + 1)) = *(uint4*)&hx[4];
        load_tile(0, 0);   // B only
        CPA_COMMIT();
    } else {
        load_tile(0, 0);
        CPA_COMMIT();
        if (NT > 1) { load_tile(1, 1); CPA_COMMIT(); }
    }

    // per-lane ldmatrix address components
    const int lr  = (lane & 7) | (((lane >> 3) & 1) << 3);
    const int lkc = lane >> 4;

#pragma unroll 1
    for (int kt = 0; kt < NT; kt++) {
        if (kt + 1 < NT) { CPA_WAIT(1); } else { CPA_WAIT(0); }
        __syncthreads();

        const uint32_t base = smem_u + (kt % 3) * STAGE_SZ;
        uint32_t aA[4], bhA[2], blA[2];
#pragma unroll
        for (int mi = 0; mi < 4; mi++)
            aA[mi] = base + soff(wm * 64 + mi * 16 + lr, lkc);
#pragma unroll
        for (int ng = 0; ng < 2; ng++) {
            int rb = wn * 32 + ng * 16 + lr;
            bhA[ng] = base + 8192  + soff(rb, lkc);
            blA[ng] = base + 16384 + soff(rb, lkc);
        }

#pragma unroll
        for (int ks = 0; ks < 2; ks++) {
            const uint32_t xo = ks * 32;    // k16 step flips bit1 of chunk idx
            uint32_t ar[4][4];
#pragma unroll
            for (int mi = 0; mi < 4; mi++) LDSM4(ar[mi], aA[mi] ^ xo);
#pragma unroll
            for (int ng = 0; ng < 2; ng++) {
                uint32_t bh4[4];
                LDSM4(bh4, bhA[ng] ^ xo);
#pragma unroll
                for (int mi = 0; mi < 4; mi++) {
                    mma_f16(acc[mi][ng*2],   ar[mi], bh4[0], bh4[2]);
                    mma_f16(acc[mi][ng*2+1], ar[mi], bh4[1], bh4[3]);
                }
                if constexpr (BLO) {
                    uint32_t bl4[4];
                    LDSM4(bl4, blA[ng] ^ xo);
#pragma unroll
                    for (int mi = 0; mi < 4; mi++) {
                        mma_f16(acc[mi][ng*2],   ar[mi], bl4[0], bl4[2]);
                        mma_f16(acc[mi][ng*2+1], ar[mi], bl4[1], bl4[3]);
                    }
                }
            }
        }

        if (kt + 2 < NT) {
            load_tile((kt + 2) % 3, kt + 2);
            CPA_COMMIT();
        }
    }

    // ---- epilogue (direct fragment stores) ----
    const int r = lane >> 2, c2 = lane & 3;
#pragma unroll
    for (int mi = 0; mi < 4; mi++) {
#pragma unroll
        for (int nj = 0; nj < 4; nj++) {
            int row = row0 + wm * 64 + mi * 16 + r;
            int col = cb * 128 + wn * 32 + nj * 8 + c2 * 2;
            float b0 = 0.f, b1 = 0.f;
            if (GELU) { b0 = bias[col]; b1 = bias[col + 1]; }
            float x0 = acc[mi][nj][0] + b0;
            float x1 = acc[mi][nj][1] + b1;
            float x2 = acc[mi][nj][2] + b0;
            float x3 = acc[mi][nj][3] + b1;
            if constexpr (GELU) {
                x0 = gelu_exact(x0); x1 = gelu_exact(x1);
                x2 = gelu_exact(x2); x3 = gelu_exact(x3);
                *(__half2*)&Ch[(size_t)row * ldc + col] =
                    __float22half2_rn(make_float2(x0, x1));
                *(__half2*)&Ch[(size_t)(row + 8) * ldc + col] =
                    __float22half2_rn(make_float2(x2, x3));
            } else {
                *(float2*)&Cf[(size_t)row * ldc + col]       = make_float2(x0, x1);
                *(float2*)&Cf[(size_t)(row + 8) * ldc + col] = make_float2(x2, x3);
            }
        }
    }
}

// ---------------------------------------------------------------------------
// Tail: per edge e,
//   tmp[j=i*3+n][dd] = sum_d f[i,d] * basis[d, n*3+dd]       (48 x 3)
//   out[o][dd]       = sum_j RP[e, o*48 + j] * tmp[j][dd]    (16 x 3)
// ---------------------------------------------------------------------------
__global__ __launch_bounds__(256)
void tail_kernel(const float* __restrict__ RP, const float* __restrict__ feats,
                 const float* __restrict__ basis, float* __restrict__ out)
{
    __shared__ float sT[16][145];
    __shared__ float sF[16][48];
    __shared__ float sBA[16][27];

    const int tid = threadIdx.x;
    const int el  = tid >> 4;
    const int o   = tid & 15;
    const size_t e = (size_t)blockIdx.x * 16 + el;

    const float* fe = feats + e * 48;
    sF[el][o*3+0] = fe[o*3+0];
    sF[el][o*3+1] = fe[o*3+1];
    sF[el][o*3+2] = fe[o*3+2];
    const float* be = basis + e * 27;
    for (int idx = o; idx < 27; idx += 16) sBA[el][idx] = be[idx];
    __syncthreads();

#pragma unroll
    for (int jj = 0; jj < 3; jj++) {
        int j = o + jj * 16;
        int i = j / 3, n = j - i * 3;
        float f0 = sF[el][i*3+0], f1 = sF[el][i*3+1], f2 = sF[el][i*3+2];
#pragma unroll
        for (int dd = 0; dd < 3; dd++) {
            sT[el][j*3 + dd] = f0 * sBA[el][n*3 + dd]
                             + f1 * sBA[el][9 + n*3 + dd]
                             + f2 * sBA[el][18 + n*3 + dd];
        }
    }
    __syncthreads();

    const float4* rp4 = (const float4*)(RP + e * RPN + o * 48);
    float s0 = 0.f, s1 = 0.f, s2 = 0.f;
    const float* tp = sT[el];
#pragma unroll
    for (int q = 0; q < 12; q++) {
        float4 rv = rp4[q];
        int j = q * 4;
        s0 = fmaf(rv.x, tp[(j+0)*3+0], s0);
        s1 = fmaf(rv.x, tp[(j+0)*3+1], s1);
        s2 = fmaf(rv.x, tp[(j+0)*3+2], s2);
        s0 = fmaf(rv.y, tp[(j+1)*3+0], s0);
        s1 = fmaf(rv.y, tp[(j+1)*3+1], s1);
        s2 = fmaf(rv.y, tp[(j+1)*3+2], s2);
        s0 = fmaf(rv.z, tp[(j+2)*3+0], s0);
        s1 = fmaf(rv.z, tp[(j+2)*3+1], s1);
        s2 = fmaf(rv.z, tp[(j+2)*3+2], s2);
        s0 = fmaf(rv.w, tp[(j+3)*3+0], s0);
        s1 = fmaf(rv.w, tp[(j+3)*3+1], s1);
        s2 = fmaf(rv.w, tp[(j+3)*3+2], s2);
    }
    float* op = out + (e * 16 + o) * 3;
    op[0] = s0; op[1] = s1; op[2] = s2;
}

// ---------------------------------------------------------------------------
extern "C" void kernel_launch(void* const* d_in, const int* in_sizes, int n_in,
                              void* d_out, int out_size)
{
    const float* edges = (const float*)d_in[0];
    const float* feats = (const float*)d_in[1];
    const float* basis = (const float*)d_in[2];
    const float* W1    = (const float*)d_in[3];
    const float* b1    = (const float*)d_in[4];
    const float* W2    = (const float*)d_in[5];
    const float* b2    = (const float*)d_in[6];
    const float* W3    = (const float*)d_in[7];
    float* out = (float*)d_out;

    __half *W1h, *W1l, *W2h, *W3h, *H1, *H2;
    float *RP;
    cudaGetSymbolAddress((void**)&W1h, g_W1h);
    cudaGetSymbolAddress((void**)&W1l, g_W1l);
    cudaGetSymbolAddress((void**)&W2h, g_W2h);
    cudaGetSymbolAddress((void**)&W3h, g_W3h);
    cudaGetSymbolAddress((void**)&H1,  g_H1);
    cudaGetSymbolAddress((void**)&H2,  g_H2);
    cudaGetSymbolAddress((void**)&RP,  g_RP);

    cudaFuncSetAttribute(hgemm<1, true,  true,  true>,
                         cudaFuncAttributeMaxDynamicSharedMemorySize, SMEM_SZ);
    cudaFuncSetAttribute(hgemm<8, true,  false, false>,
                         cudaFuncAttributeMaxDynamicSharedMemorySize, SMEM_SZ);
    cudaFuncSetAttribute(hgemm<8, false, false, false>,
                         cudaFuncAttributeMaxDynamicSharedMemorySize, SMEM_SZ);

    // weight prep (transpose; hi/lo only for W1)
    prep_weight<<<(256 * 32 + 255) / 256, 256>>>(W1, 32, 256, 256, 0, W1h, W1l);
    prep_weight<<<(256 * 256 + 255) / 256, 256>>>(W2, 256, 256, 256, 0, W2h, nullptr);
    prep_weight<<<(768 * 256 + 255) / 256, 256>>>(W3, 256, 768, 1536, W3OFF, W3h, nullptr);

    dim3 blk(256);
    // layer 1: gelu(edges @ W1 + b1) -> H1 fp16  (2-pass exact weights)
    hgemm<1, true, true, true><<<dim3(E_TOTAL / 128, 2), blk, SMEM_SZ>>>(
        edges, nullptr, 32, W1h, W1l, 32, b1, nullptr, H1, 256);
    // layer 2: gelu(H1 @ W2 + b2) -> H2 fp16  (hi-only)
    hgemm<8, true, false, false><<<dim3(E_TOTAL / 128, 2), blk, SMEM_SZ>>>(
        nullptr, H1, 256, W2h, nullptr, 256, b2, nullptr, H2, 256);
    // layer 3: H2 @ W3[:,768:1536] -> RP fp32  (hi-only, 6 chunks of 128)
    hgemm<8, false, false, false><<<dim3(E_TOTAL / 128, 6), blk, SMEM_SZ>>>(
        nullptr, H2, 256, W3h, nullptr, 256, nullptr, RP, nullptr, RPN);
    // tail
    tail_kernel<<<E_TOTAL / 16, blk>>>(RP, feats, basis, out);
}

// round 8
// speedup vs baseline: 2.9372x; 1.1273x over previous
#include <cuda_runtime.h>
#include <cuda_fp16.h>
#include <math.h>
#include <stdint.h>

#define E_TOTAL 65536     // B*N*K
#define W3OFF   768       // SPLIT_OFF
#define RPN     768       // SPLIT_SZ

// ---- device scratch ----
// weights transposed [N][K], fp16 (hi, + lo only used for W1)
__device__ __half g_W1h[256 * 32],  g_W1l[256 * 32];
__device__ __half g_W2h[256 * 256];
__device__ __half g_W3h[768 * 256];
// activations [E][256] plain fp16
__device__ __half g_H1[(size_t)E_TOTAL * 256];
__device__ __half g_H2[(size_t)E_TOTAL * 256];
__device__ __half g_RP[(size_t)E_TOTAL * RPN];   // fp16 RP (100 MB)

__device__ __forceinline__ float gelu_exact(float x) {
    return 0.5f * x * (1.0f + erff(x * 0.70710678118654752440f));
}

// ---------------------------------------------------------------------------
#define CPA16(dst_u32, src_ptr) \
    asm volatile("cp.async.cg.shared.global [%0], [%1], 16;" :: "r"(dst_u32), "l"(src_ptr))
#define CPA_COMMIT() asm volatile("cp.async.commit_group;" ::: "memory")
#define CPA_WAIT(n)  asm volatile("cp.async.wait_group %0;" :: "n"(n) : "memory")

#define LDSM4(R, addr)                                                        \
    asm volatile("ldmatrix.sync.aligned.m8n8.x4.shared.b16 {%0,%1,%2,%3}, [%4];" \
                 : "=r"((R)[0]), "=r"((R)[1]), "=r"((R)[2]), "=r"((R)[3])     \
                 : "r"(addr))

__device__ __forceinline__ void mma_f16(float* d, const uint32_t* a,
                                        uint32_t b0, uint32_t b1) {
    asm volatile(
        "mma.sync.aligned.m16n8k16.row.col.f32.f16.f16.f32 "
        "{%0,%1,%2,%3}, {%4,%5,%6,%7}, {%8,%9}, {%0,%1,%2,%3};"
        : "+f"(d[0]), "+f"(d[1]), "+f"(d[2]), "+f"(d[3])
        : "r"(a[0]), "r"(a[1]), "r"(a[2]), "r"(a[3]), "r"(b0), "r"(b1));
}

// swizzled byte offset for 64B rows (4 chunks of 16B); conflict-free for
// cp.async stores AND ldmatrix phases (validated in R4/R6/R7).
__device__ __forceinline__ uint32_t soff(int r, int c) {
    return (uint32_t)((r * 4 + (c ^ ((r >> 1) & 3))) << 4);
}

// ---------------------------------------------------------------------------
// prep: transpose + fp16 hi(/lo) split weights. out[n*K+k] from W[k*ldw+coff+n]
// ---------------------------------------------------------------------------
__global__ void prep_weight(const float* __restrict__ W, int K, int N, int ldw,
                            int coff, __half* __restrict__ hi, __half* __restrict__ lo)
{
    int idx = blockIdx.x * 256 + threadIdx.x;
    if (idx >= N * K) return;
    int n = idx / K, k = idx - n * K;
    float v = W[(size_t)k * ldw + coff + n];
    __half h = __float2half_rn(v);
    hi[idx] = h;
    if (lo) lo[idx] = __float2half_rn(v - __half2float(h));
}

// ---------------------------------------------------------------------------
// fp16 HMMA GEMM. BLO: add weight-lo pass (2-pass exact weights).
// GELU: bias+gelu, write fp16 activations; else raw accum, write fp16 C.
// BM=128 BN=128 BK=32, 3-stage cp.async pipeline, 8 warps (2m x 4n), warp 64x32.
// smem stage (24576B): A @0 (8K), Bh @8192 (8K), Bl @16384 (8K, only if BLO)
// ---------------------------------------------------------------------------
#define STAGE_SZ 24576
#define SMEM_SZ  (3 * STAGE_SZ)

template<int NT, bool GELU, bool AFP32, bool BLO>
__global__ __launch_bounds__(256, 2)
void hgemm(const float* __restrict__ Af, const __half* __restrict__ Ain, int lda,
           const __half* __restrict__ Bh, const __half* __restrict__ Bl, int ldb,
           const float* __restrict__ bias,
           __half* __restrict__ Ch, int ldc)
{
    extern __shared__ __align__(128) char smem_c[];
    const uint32_t smem_u = (uint32_t)__cvta_generic_to_shared(smem_c);

    const int tid  = threadIdx.x;
    const int wid  = tid >> 5;
    const int lane = tid & 31;
    const int wm   = wid >> 2;      // 0..1
    const int wn   = wid & 3;       // 0..3
    const int row0 = blockIdx.x * 128;
    const int cb   = blockIdx.y;

    float acc[4][4][4];
#pragma unroll
    for (int i = 0; i < 4; i++)
#pragma unroll
        for (int j = 0; j < 4; j++)
#pragma unroll
            for (int q = 0; q < 4; q++) acc[i][j][q] = 0.f;

    // loader indices: 512 16B-chunks per 128x32 tile, 2 per thread
    const int lr0 = tid >> 2, lc0 = tid & 3;
    const int lr1 = (tid + 256) >> 2, lc1 = lc0;

    auto load_tile = [&](int s, int kt) {
        const uint32_t base = smem_u + s * STAGE_SZ;
        if constexpr (!AFP32) {
            CPA16(base + soff(lr0, lc0),
                  Ain + (size_t)(row0 + lr0) * lda + kt * 32 + lc0 * 8);
            CPA16(base + soff(lr1, lc1),
                  Ain + (size_t)(row0 + lr1) * lda + kt * 32 + lc1 * 8);
        }
        CPA16(base + 8192 + soff(lr0, lc0),
              Bh + (size_t)(cb * 128 + lr0) * ldb + kt * 32 + lc0 * 8);
        CPA16(base + 8192 + soff(lr1, lc1),
              Bh + (size_t)(cb * 128 + lr1) * ldb + kt * 32 + lc1 * 8);
        if constexpr (BLO) {
            CPA16(base + 16384 + soff(lr0, lc0),
                  Bl + (size_t)(cb * 128 + lr0) * ldb + kt * 32 + lc0 * 8);
            CPA16(base + 16384 + soff(lr1, lc1),
                  Bl + (size_t)(cb * 128 + lr1) * ldb + kt * 32 + lc1 * 8);
        }
    };

    if constexpr (AFP32) {
        // fp32 A (K=32, single tile): convert to fp16 into stage 0
        int r = tid >> 1, hf = tid & 1;
        const float4* s4 = (const float4*)(Af + (size_t)(row0 + r) * lda + hf * 16);
        __half2 hx[8];
#pragma unroll
        for (int q = 0; q < 4; q++) {
            float4 v = s4[q];
            hx[2*q]   = __float22half2_rn(make_float2(v.x, v.y));
            hx[2*q+1] = __float22half2_rn(make_float2(v.z, v.w));
        }
        *(uint4*)(smem_c + soff(r, hf * 2))     = *(uint4*)&hx[0];
        *(uint4*)(smem_c + soff(r, hf * 2 + 1)) = *(uint4*)&hx[4];
        load_tile(0, 0);   // B only
        CPA_COMMIT();
    } else {
        load_tile(0, 0);
        CPA_COMMIT();
        if (NT > 1) { load_tile(1, 1); CPA_COMMIT(); }
    }

    // per-lane ldmatrix address components
    const int lr  = (lane & 7) | (((lane >> 3) & 1) << 3);
    const int lkc = lane >> 4;

#pragma unroll 1
    for (int kt = 0; kt < NT; kt++) {
        if (kt + 1 < NT) { CPA_WAIT(1); } else { CPA_WAIT(0); }
        __syncthreads();

        const uint32_t base = smem_u + (kt % 3) * STAGE_SZ;
        uint32_t aA[4], bhA[2], blA[2];
#pragma unroll
        for (int mi = 0; mi < 4; mi++)
            aA[mi] = base + soff(wm * 64 + mi * 16 + lr, lkc);
#pragma unroll
        for (int ng = 0; ng < 2; ng++) {
            int rb = wn * 32 + ng * 16 + lr;
            bhA[ng] = base + 8192  + soff(rb, lkc);
            blA[ng] = base + 16384 + soff(rb, lkc);
        }

#pragma unroll
        for (int ks = 0; ks < 2; ks++) {
            const uint32_t xo = ks * 32;    // k16 step flips bit1 of chunk idx
            uint32_t ar[4][4];
#pragma unroll
            for (int mi = 0; mi < 4; mi++) LDSM4(ar[mi], aA[mi] ^ xo);
#pragma unroll
            for (int ng = 0; ng < 2; ng++) {
                uint32_t bh4[4];
                LDSM4(bh4, bhA[ng] ^ xo);
#pragma unroll
                for (int mi = 0; mi < 4; mi++) {
                    mma_f16(acc[mi][ng*2],   ar[mi], bh4[0], bh4[2]);
                    mma_f16(acc[mi][ng*2+1], ar[mi], bh4[1], bh4[3]);
                }
                if constexpr (BLO) {
                    uint32_t bl4[4];
                    LDSM4(bl4, blA[ng] ^ xo);
#pragma unroll
                    for (int mi = 0; mi < 4; mi++) {
                        mma_f16(acc[mi][ng*2],   ar[mi], bl4[0], bl4[2]);
                        mma_f16(acc[mi][ng*2+1], ar[mi], bl4[1], bl4[3]);
                    }
                }
            }
        }

        if (kt + 2 < NT) {
            load_tile((kt + 2) % 3, kt + 2);
            CPA_COMMIT();
        }
    }

    // ---- epilogue (direct fragment stores, fp16 out) ----
    const int r = lane >> 2, c2 = lane & 3;
#pragma unroll
    for (int mi = 0; mi < 4; mi++) {
#pragma unroll
        for (int nj = 0; nj < 4; nj++) {
            int row = row0 + wm * 64 + mi * 16 + r;
            int col = cb * 128 + wn * 32 + nj * 8 + c2 * 2;
            float b0 = 0.f, b1 = 0.f;
            if (GELU) { b0 = bias[col]; b1 = bias[col + 1]; }
            float x0 = acc[mi][nj][0] + b0;
            float x1 = acc[mi][nj][1] + b1;
            float x2 = acc[mi][nj][2] + b0;
            float x3 = acc[mi][nj][3] + b1;
            if constexpr (GELU) {
                x0 = gelu_exact(x0); x1 = gelu_exact(x1);
                x2 = gelu_exact(x2); x3 = gelu_exact(x3);
            }
            *(__half2*)&Ch[(size_t)row * ldc + col] =
                __float22half2_rn(make_float2(x0, x1));
            *(__half2*)&Ch[(size_t)(row + 8) * ldc + col] =
                __float22half2_rn(make_float2(x2, x3));
        }
    }
}

// ---------------------------------------------------------------------------
// Tail: per edge e,
//   tmp[j=i*3+n][dd] = sum_d f[i,d] * basis[d, n*3+dd]       (48 x 3)
//   out[o][dd]       = sum_j RP[e, o*48 + j] * tmp[j][dd]    (16 x 3)
// Block = 16 edges x 16 threads. RP is fp16.
// ---------------------------------------------------------------------------
__global__ __launch_bounds__(256)
void tail_kernel(const __half* __restrict__ RP, const float* __restrict__ feats,
                 const float* __restrict__ basis, float* __restrict__ out)
{
    __shared__ float sT[16][145];
    __shared__ float sF[16][48];
    __shared__ float sBA[16][27];

    const int tid = threadIdx.x;
    const int el  = tid >> 4;
    const int o   = tid & 15;
    const size_t e = (size_t)blockIdx.x * 16 + el;

    const float* fe = feats + e * 48;
    sF[el][o*3+0] = fe[o*3+0];
    sF[el][o*3+1] = fe[o*3+1];
    sF[el][o*3+2] = fe[o*3+2];
    const float* be = basis + e * 27;
    for (int idx = o; idx < 27; idx += 16) sBA[el][idx] = be[idx];
    __syncthreads();

#pragma unroll
    for (int jj = 0; jj < 3; jj++) {
        int j = o + jj * 16;
        int i = j / 3, n = j - i * 3;
        float f0 = sF[el][i*3+0], f1 = sF[el][i*3+1], f2 = sF[el][i*3+2];
#pragma unroll
        for (int dd = 0; dd < 3; dd++) {
            sT[el][j*3 + dd] = f0 * sBA[el][n*3 + dd]
                             + f1 * sBA[el][9 + n*3 + dd]
                             + f2 * sBA[el][18 + n*3 + dd];
        }
    }
    __syncthreads();

    // 48 fp16 values = 6 x uint4 (8 halves each)
    const uint4* rp4 = (const uint4*)(RP + e * RPN + o * 48);
    float s0 = 0.f, s1 = 0.f, s2 = 0.f;
    const float* tp = sT[el];
#pragma unroll
    for (int q = 0; q < 6; q++) {
        uint4 u = rp4[q];
        const __half2* hp = (const __half2*)&u;
#pragma unroll
        for (int p = 0; p < 4; p++) {
            float2 fv = __half22float2(hp[p]);
            int j = q * 8 + p * 2;
            s0 = fmaf(fv.x, tp[j*3+0], s0);
            s1 = fmaf(fv.x, tp[j*3+1], s1);
            s2 = fmaf(fv.x, tp[j*3+2], s2);
            s0 = fmaf(fv.y, tp[(j+1)*3+0], s0);
            s1 = fmaf(fv.y, tp[(j+1)*3+1], s1);
            s2 = fmaf(fv.y, tp[(j+1)*3+2], s2);
        }
    }
    float* op = out + (e * 16 + o) * 3;
    op[0] = s0; op[1] = s1; op[2] = s2;
}

// ---------------------------------------------------------------------------
extern "C" void kernel_launch(void* const* d_in, const int* in_sizes, int n_in,
                              void* d_out, int out_size)
{
    const float* edges = (const float*)d_in[0];
    const float* feats = (const float*)d_in[1];
    const float* basis = (const float*)d_in[2];
    const float* W1    = (const float*)d_in[3];
    const float* b1    = (const float*)d_in[4];
    const float* W2    = (const float*)d_in[5];
    const float* b2    = (const float*)d_in[6];
    const float* W3    = (const float*)d_in[7];
    float* out = (float*)d_out;

    __half *W1h, *W1l, *W2h, *W3h, *H1, *H2, *RP;
    cudaGetSymbolAddress((void**)&W1h, g_W1h);
    cudaGetSymbolAddress((void**)&W1l, g_W1l);
    cudaGetSymbolAddress((void**)&W2h, g_W2h);
    cudaGetSymbolAddress((void**)&W3h, g_W3h);
    cudaGetSymbolAddress((void**)&H1,  g_H1);
    cudaGetSymbolAddress((void**)&H2,  g_H2);
    cudaGetSymbolAddress((void**)&RP,  g_RP);

    cudaFuncSetAttribute(hgemm<1, true,  true,  true>,
                         cudaFuncAttributeMaxDynamicSharedMemorySize, SMEM_SZ);
    cudaFuncSetAttribute(hgemm<8, true,  false, false>,
                         cudaFuncAttributeMaxDynamicSharedMemorySize, SMEM_SZ);
    cudaFuncSetAttribute(hgemm<8, false, false, false>,
                         cudaFuncAttributeMaxDynamicSharedMemorySize, SMEM_SZ);

    // weight prep (transpose; hi/lo only for W1)
    prep_weight<<<(256 * 32 + 255) / 256, 256>>>(W1, 32, 256, 256, 0, W1h, W1l);
    prep_weight<<<(256 * 256 + 255) / 256, 256>>>(W2, 256, 256, 256, 0, W2h, nullptr);
    prep_weight<<<(768 * 256 + 255) / 256, 256>>>(W3, 256, 768, 1536, W3OFF, W3h, nullptr);

    dim3 blk(256);
    // layer 1: gelu(edges @ W1 + b1) -> H1 fp16  (2-pass exact weights)
    hgemm<1, true, true, true><<<dim3(E_TOTAL / 128, 2), blk, SMEM_SZ>>>(
        edges, nullptr, 32, W1h, W1l, 32, b1, H1, 256);
    // layer 2: gelu(H1 @ W2 + b2) -> H2 fp16  (hi-only)
    hgemm<8, true, false, false><<<dim3(E_TOTAL / 128, 2), blk, SMEM_SZ>>>(
        nullptr, H1, 256, W2h, nullptr, 256, b2, H2, 256);
    // layer 3: H2 @ W3[:,768:1536] -> RP fp16  (hi-only, 6 chunks of 128)
    hgemm<8, false, false, false><<<dim3(E_TOTAL / 128, 6), blk, SMEM_SZ>>>(
        nullptr, H2, 256, W3h, nullptr, 256, nullptr, RP, RPN);
    // tail
    tail_kernel<<<E_TOTAL / 16, blk>>>(RP, feats, basis, out);
}

// round 9
// speedup vs baseline: 2.9527x; 1.0053x over previous
#include <cuda_runtime.h>
#include <cuda_fp16.h>
#include <math.h>
#include <stdint.h>

#define E_TOTAL 65536     // B*N*K
#define W3OFF   768       // SPLIT_OFF
#define RPN     768       // SPLIT_SZ

// ---- device scratch ----
__device__ __half g_W1h[256 * 32],  g_W1l[256 * 32];
__device__ __half g_W2h[256 * 256];
__device__ __half g_W3h[768 * 256];
__device__ __half g_H2[(size_t)E_TOTAL * 256];
__device__ __half g_RP[(size_t)E_TOTAL * RPN];   // fp16 RP (100 MB)

__device__ __forceinline__ float gelu_exact(float x) {
    return 0.5f * x * (1.0f + erff(x * 0.70710678118654752440f));
}

// ---------------------------------------------------------------------------
#define CPA16(dst_u32, src_ptr) \
    asm volatile("cp.async.cg.shared.global [%0], [%1], 16;" :: "r"(dst_u32), "l"(src_ptr))
#define CPA_COMMIT() asm volatile("cp.async.commit_group;" ::: "memory")
#define CPA_WAIT(n)  asm volatile("cp.async.wait_group %0;" :: "n"(n) : "memory")

#define LDSM4(R, addr)                                                        \
    asm volatile("ldmatrix.sync.aligned.m8n8.x4.shared.b16 {%0,%1,%2,%3}, [%4];" \
                 : "=r"((R)[0]), "=r"((R)[1]), "=r"((R)[2]), "=r"((R)[3])     \
                 : "r"(addr))

__device__ __forceinline__ void mma_f16(float* d, const uint32_t* a,
                                        uint32_t b0, uint32_t b1) {
    asm volatile(
        "mma.sync.aligned.m16n8k16.row.col.f32.f16.f16.f32 "
        "{%0,%1,%2,%3}, {%4,%5,%6,%7}, {%8,%9}, {%0,%1,%2,%3};"
        : "+f"(d[0]), "+f"(d[1]), "+f"(d[2]), "+f"(d[3])
        : "r"(a[0]), "r"(a[1]), "r"(a[2]), "r"(a[3]), "r"(b0), "r"(b1));
}

// swizzled byte offset for 64B rows (4 chunks of 16B); conflict-free for
// cp.async stores AND ldmatrix phases (validated R4/R6/R7/R8).
__device__ __forceinline__ uint32_t soff(int r, int c) {
    return (uint32_t)((r * 4 + (c ^ ((r >> 1) & 3))) << 4);
}

// ---------------------------------------------------------------------------
__global__ void prep_weight(const float* __restrict__ W, int K, int N, int ldw,
                            int coff, __half* __restrict__ hi, __half* __restrict__ lo)
{
    int idx = blockIdx.x * 256 + threadIdx.x;
    if (idx >= N * K) return;
    int n = idx / K, k = idx - n * K;
    float v = W[(size_t)k * ldw + coff + n];
    __half h = __float2half_rn(v);
    hi[idx] = h;
    if (lo) lo[idx] = __float2half_rn(v - __half2float(h));
}

// ---------------------------------------------------------------------------
// Fused GEMM1+GEMM2: per CTA (grid = E/128 x 2):
//   phase A: H1tile[128x256] = gelu(edges[128x32] @ (W1h+W1l) + b1) -> smem
//            (two 128-col passes, 2-pass exact weights)
//   phase B: H2[128 x 128-chunk] = gelu(H1tile @ W2h + b2) -> global fp16
// smem: H1 k-tiles 8x8192=64KB @0;  region1 @65536: 3x8192 stages
//   (phase A uses region1 as [edgesA | W1h | W1l])
// ---------------------------------------------------------------------------
#define R1OFF 65536
#define SM12  (R1OFF + 3 * 8192)

__global__ __launch_bounds__(256, 2)
void hgemm12(const float* __restrict__ edges,
             const __half* __restrict__ W1h, const __half* __restrict__ W1l,
             const __half* __restrict__ W2h,
             const float* __restrict__ b1, const float* __restrict__ b2,
             __half* __restrict__ H2)
{
    extern __shared__ __align__(128) char smem_c[];
    const uint32_t smem_u = (uint32_t)__cvta_generic_to_shared(smem_c);

    const int tid  = threadIdx.x;
    const int wid  = tid >> 5;
    const int lane = tid & 31;
    const int wm   = wid >> 2;      // 0..1
    const int wn   = wid & 3;       // 0..3
    const int row0 = blockIdx.x * 128;
    const int cb   = blockIdx.y;

    const uint32_t edgesB = smem_u + R1OFF;
    const uint32_t w1hB   = smem_u + R1OFF + 8192;
    const uint32_t w1lB   = smem_u + R1OFF + 16384;

    // per-lane ldmatrix components
    const int lr  = (lane & 7) | (((lane >> 3) & 1) << 3);
    const int lkc = lane >> 4;
    const int r4  = lane >> 2, c2 = lane & 3;

    float acc[4][4][4];
    auto zero_acc = [&]() {
#pragma unroll
        for (int i = 0; i < 4; i++)
#pragma unroll
            for (int j = 0; j < 4; j++)
#pragma unroll
                for (int q = 0; q < 4; q++) acc[i][j][q] = 0.f;
    };

    // ---- phase A: edges -> fp16 smem; W1 half0 ----
    {
        int r = tid >> 1, hf = tid & 1;
        const float4* s4 = (const float4*)(edges + (size_t)(row0 + r) * 32 + hf * 16);
        __half2 hx[8];
#pragma unroll
        for (int q = 0; q < 4; q++) {
            float4 v = s4[q];
            hx[2*q]   = __float22half2_rn(make_float2(v.x, v.y));
            hx[2*q+1] = __float22half2_rn(make_float2(v.z, v.w));
        }
        *(uint4*)(smem_c + R1OFF + soff(r, hf * 2))     = *(uint4*)&hx[0];
        *(uint4*)(smem_c + R1OFF + soff(r, hf * 2 + 1)) = *(uint4*)&hx[4];
    }
    const int lr0 = tid >> 2, lc0 = tid & 3;
    const int lr1 = (tid + 256) >> 2, lc1 = lc0;

    auto loadW1 = [&](int h) {
        CPA16(w1hB + soff(lr0, lc0), W1h + (size_t)(h * 128 + lr0) * 32 + lc0 * 8);
        CPA16(w1hB + soff(lr1, lc1), W1h + (size_t)(h * 128 + lr1) * 32 + lc1 * 8);
        CPA16(w1lB + soff(lr0, lc0), W1l + (size_t)(h * 128 + lr0) * 32 + lc0 * 8);
        CPA16(w1lB + soff(lr1, lc1), W1l + (size_t)(h * 128 + lr1) * 32 + lc1 * 8);
    };

    auto mmaA = [&]() {
#pragma unroll
        for (int ks = 0; ks < 2; ks++) {
            const uint32_t xo = ks * 32;
            uint32_t ar[4][4];
#pragma unroll
            for (int mi = 0; mi < 4; mi++)
                LDSM4(ar[mi], (edgesB + soff(wm * 64 + mi * 16 + lr, lkc)) ^ xo);
#pragma unroll
            for (int ng = 0; ng < 2; ng++) {
                int rb = wn * 32 + ng * 16 + lr;
                uint32_t bh4[4], bl4[4];
                LDSM4(bh4, (w1hB + soff(rb, lkc)) ^ xo);
                LDSM4(bl4, (w1lB + soff(rb, lkc)) ^ xo);
#pragma unroll
                for (int mi = 0; mi < 4; mi++) {
                    mma_f16(acc[mi][ng*2],   ar[mi], bh4[0], bh4[2]);
                    mma_f16(acc[mi][ng*2+1], ar[mi], bh4[1], bh4[3]);
                    mma_f16(acc[mi][ng*2],   ar[mi], bl4[0], bl4[2]);
                    mma_f16(acc[mi][ng*2+1], ar[mi], bl4[1], bl4[3]);
                }
            }
        }
    };

    // epilogue A: acc -> gelu -> fp16 -> H1 k-tiles in smem
    auto epiA = [&](int h) {
#pragma unroll
        for (int mi = 0; mi < 4; mi++) {
#pragma unroll
            for (int nj = 0; nj < 4; nj++) {
                int rloc = wm * 64 + mi * 16 + r4;
                int col  = h * 128 + wn * 32 + nj * 8 + c2 * 2;
                float bb0 = b1[col], bb1 = b1[col + 1];
                float x0 = gelu_exact(acc[mi][nj][0] + bb0);
                float x1 = gelu_exact(acc[mi][nj][1] + bb1);
                float x2 = gelu_exact(acc[mi][nj][2] + bb0);
                float x3 = gelu_exact(acc[mi][nj][3] + bb1);
                int ktile = col >> 5, kc = col & 31;
                uint32_t a0 = (uint32_t)(ktile * 8192) + soff(rloc, kc >> 3) + (kc & 7) * 2;
                uint32_t a1 = (uint32_t)(ktile * 8192) + soff(rloc + 8, kc >> 3) + (kc & 7) * 2;
                *(__half2*)(smem_c + a0) = __float22half2_rn(make_float2(x0, x1));
                *(__half2*)(smem_c + a1) = __float22half2_rn(make_float2(x2, x3));
            }
        }
    };

    loadW1(0);
    CPA_COMMIT();
    zero_acc();
    CPA_WAIT(0);
    __syncthreads();
    mmaA();                 // half 0
    __syncthreads();        // all warps done with W1 half0 bufs
    loadW1(1);
    CPA_COMMIT();
    epiA(0);                // overlaps with W1 half1 loads
    zero_acc();
    CPA_WAIT(0);
    __syncthreads();
    mmaA();                 // half 1
    __syncthreads();        // all warps done with region1 (edges+W1)

    // ---- phase B: prefetch W2 stages 0,1 into region1, epilogue A half1 ----
    auto loadW2 = [&](int s, int kt) {
        const uint32_t base = smem_u + R1OFF + s * 8192;
        CPA16(base + soff(lr0, lc0), W2h + (size_t)(cb * 128 + lr0) * 256 + kt * 32 + lc0 * 8);
        CPA16(base + soff(lr1, lc1), W2h + (size_t)(cb * 128 + lr1) * 256 + kt * 32 + lc1 * 8);
    };
    loadW2(0, 0); CPA_COMMIT();
    loadW2(1, 1); CPA_COMMIT();
    epiA(1);
    zero_acc();

#pragma unroll 1
    for (int kt = 0; kt < 8; kt++) {
        if (kt + 1 < 8) { CPA_WAIT(1); } else { CPA_WAIT(0); }
        __syncthreads();

        const uint32_t aB = smem_u + kt * 8192;                 // H1 k-tile
        const uint32_t bB = smem_u + R1OFF + (kt % 3) * 8192;   // W2 stage
#pragma unroll
        for (int ks = 0; ks < 2; ks++) {
            const uint32_t xo = ks * 32;
            uint32_t ar[4][4];
#pragma unroll
            for (int mi = 0; mi < 4; mi++)
                LDSM4(ar[mi], (aB + soff(wm * 64 + mi * 16 + lr, lkc)) ^ xo);
#pragma unroll
            for (int ng = 0; ng < 2; ng++) {
                uint32_t bh4[4];
                LDSM4(bh4, (bB + soff(wn * 32 + ng * 16 + lr, lkc)) ^ xo);
#pragma unroll
                for (int mi = 0; mi < 4; mi++) {
                    mma_f16(acc[mi][ng*2],   ar[mi], bh4[0], bh4[2]);
                    mma_f16(acc[mi][ng*2+1], ar[mi], bh4[1], bh4[3]);
                }
            }
        }
        if (kt + 2 < 8) {
            loadW2((kt + 2) % 3, kt + 2);
            CPA_COMMIT();
        }
    }

    // ---- epilogue B: bias+gelu -> global H2 fp16 ----
#pragma unroll
    for (int mi = 0; mi < 4; mi++) {
#pragma unroll
        for (int nj = 0; nj < 4; nj++) {
            int row = row0 + wm * 64 + mi * 16 + r4;
            int col = cb * 128 + wn * 32 + nj * 8 + c2 * 2;
            float bb0 = b2[col], bb1 = b2[col + 1];
            float x0 = gelu_exact(acc[mi][nj][0] + bb0);
            float x1 = gelu_exact(acc[mi][nj][1] + bb1);
            float x2 = gelu_exact(acc[mi][nj][2] + bb0);
            float x3 = gelu_exact(acc[mi][nj][3] + bb1);
            *(__half2*)&H2[(size_t)row * 256 + col] =
                __float22half2_rn(make_float2(x0, x1));
            *(__half2*)&H2[(size_t)(row + 8) * 256 + col] =
                __float22half2_rn(make_float2(x2, x3));
        }
    }
}

// ---------------------------------------------------------------------------
// GEMM3 (unchanged validated kernel): RP[128 x 128-chunk] = H2 @ W3h
// ---------------------------------------------------------------------------
#define STAGE_SZ 24576
#define SMEM_SZ  (3 * STAGE_SZ)

__global__ __launch_bounds__(256, 2)
void hgemm3(const __half* __restrict__ Ain,
            const __half* __restrict__ Bh,
            __half* __restrict__ Ch)
{
    extern __shared__ __align__(128) char smem_c[];
    const uint32_t smem_u = (uint32_t)__cvta_generic_to_shared(smem_c);

    const int tid  = threadIdx.x;
    const int wid  = tid >> 5;
    const int lane = tid & 31;
    const int wm   = wid >> 2;
    const int wn   = wid & 3;
    const int row0 = blockIdx.x * 128;
    const int cb   = blockIdx.y;

    float acc[4][4][4];
#pragma unroll
    for (int i = 0; i < 4; i++)
#pragma unroll
        for (int j = 0; j < 4; j++)
#pragma unroll
            for (int q = 0; q < 4; q++) acc[i][j][q] = 0.f;

    const int lr0 = tid >> 2, lc0 = tid & 3;
    const int lr1 = (tid + 256) >> 2, lc1 = lc0;

    auto load_tile = [&](int s, int kt) {
        const uint32_t base = smem_u + s * STAGE_SZ;
        CPA16(base + soff(lr0, lc0),
              Ain + (size_t)(row0 + lr0) * 256 + kt * 32 + lc0 * 8);
        CPA16(base + soff(lr1, lc1),
              Ain + (size_t)(row0 + lr1) * 256 + kt * 32 + lc1 * 8);
        CPA16(base + 8192 + soff(lr0, lc0),
              Bh + (size_t)(cb * 128 + lr0) * 256 + kt * 32 + lc0 * 8);
        CPA16(base + 8192 + soff(lr1, lc1),
              Bh + (size_t)(cb * 128 + lr1) * 256 + kt * 32 + lc1 * 8);
    };

    load_tile(0, 0); CPA_COMMIT();
    load_tile(1, 1); CPA_COMMIT();

    const int lr  = (lane & 7) | (((lane >> 3) & 1) << 3);
    const int lkc = lane >> 4;

#pragma unroll 1
    for (int kt = 0; kt < 8; kt++) {
        if (kt + 1 < 8) { CPA_WAIT(1); } else { CPA_WAIT(0); }
        __syncthreads();

        const uint32_t base = smem_u + (kt % 3) * STAGE_SZ;
#pragma unroll
        for (int ks = 0; ks < 2; ks++) {
            const uint32_t xo = ks * 32;
            uint32_t ar[4][4];
#pragma unroll
            for (int mi = 0; mi < 4; mi++)
                LDSM4(ar[mi], (base + soff(wm * 64 + mi * 16 + lr, lkc)) ^ xo);
#pragma unroll
            for (int ng = 0; ng < 2; ng++) {
                uint32_t bh4[4];
                LDSM4(bh4, (base + 8192 + soff(wn * 32 + ng * 16 + lr, lkc)) ^ xo);
#pragma unroll
                for (int mi = 0; mi < 4; mi++) {
                    mma_f16(acc[mi][ng*2],   ar[mi], bh4[0], bh4[2]);
                    mma_f16(acc[mi][ng*2+1], ar[mi], bh4[1], bh4[3]);
                }
            }
        }
        if (kt + 2 < 8) {
            load_tile((kt + 2) % 3, kt + 2);
            CPA_COMMIT();
        }
    }

    const int r = lane >> 2, c2 = lane & 3;
#pragma unroll
    for (int mi = 0; mi < 4; mi++) {
#pragma unroll
        for (int nj = 0; nj < 4; nj++) {
            int row = row0 + wm * 64 + mi * 16 + r;
            int col = cb * 128 + wn * 32 + nj * 8 + c2 * 2;
            *(__half2*)&Ch[(size_t)row * RPN + col] =
                __float22half2_rn(make_float2(acc[mi][nj][0], acc[mi][nj][1]));
            *(__half2*)&Ch[(size_t)(row + 8) * RPN + col] =
                __float22half2_rn(make_float2(acc[mi][nj][2], acc[mi][nj][3]));
        }
    }
}

// ---------------------------------------------------------------------------
// Tail: tmp stored transposed [dd][j] for vectorized broadcast loads.
//   tmp[dd][j=i*3+n] = sum_d f[i,d] * basis[d, n*3+dd]
//   out[o][dd]       = sum_j RP[e, o*48+j] * tmp[dd][j]
// Block = 16 edges x 16 threads.
// ---------------------------------------------------------------------------
__global__ __launch_bounds__(256)
void tail_kernel(const __half* __restrict__ RP, const float* __restrict__ feats,
                 const float* __restrict__ basis, float* __restrict__ out)
{
    __shared__ __align__(16) float sT[16][3][52];
    __shared__ float sF[16][48];
    __shared__ float sBA[16][27];

    const int tid = threadIdx.x;
    const int el  = tid >> 4;
    const int o   = tid & 15;
    const size_t e = (size_t)blockIdx.x * 16 + el;

    const float* fe = feats + e * 48;
    sF[el][o*3+0] = fe[o*3+0];
    sF[el][o*3+1] = fe[o*3+1];
    sF[el][o*3+2] = fe[o*3+2];
    const float* be = basis + e * 27;
    for (int idx = o; idx < 27; idx += 16) sBA[el][idx] = be[idx];
    __syncthreads();

#pragma unroll
    for (int jj = 0; jj < 3; jj++) {
        int j = o + jj * 16;
        int i = j / 3, n = j - i * 3;
        float f0 = sF[el][i*3+0], f1 = sF[el][i*3+1], f2 = sF[el][i*3+2];
#pragma unroll
        for (int dd = 0; dd < 3; dd++) {
            sT[el][dd][j] = f0 * sBA[el][n*3 + dd]
                          + f1 * sBA[el][9 + n*3 + dd]
                          + f2 * sBA[el][18 + n*3 + dd];
        }
    }
    __syncthreads();

    const uint4* rp4 = (const uint4*)(RP + e * RPN + o * 48);
    const float* t0 = &sT[el][0][0];
    const float* t1 = &sT[el][1][0];
    const float* t2 = &sT[el][2][0];
    float s0 = 0.f, s1 = 0.f, s2 = 0.f;
#pragma unroll
    for (int q = 0; q < 6; q++) {
        uint4 u = rp4[q];
        const __half2* hp = (const __half2*)&u;
        float2 f01 = __half22float2(hp[0]);
        float2 f23 = __half22float2(hp[1]);
        float2 f45 = __half22float2(hp[2]);
        float2 f67 = __half22float2(hp[3]);
        float4 a0 = *(const float4*)&t0[q*8];
        float4 a1 = *(const float4*)&t0[q*8+4];
        s0 = fmaf(f01.x, a0.x, s0); s0 = fmaf(f01.y, a0.y, s0);
        s0 = fmaf(f23.x, a0.z, s0); s0 = fmaf(f23.y, a0.w, s0);
        s0 = fmaf(f45.x, a1.x, s0); s0 = fmaf(f45.y, a1.y, s0);
        s0 = fmaf(f67.x, a1.z, s0); s0 = fmaf(f67.y, a1.w, s0);
        float4 b0 = *(const float4*)&t1[q*8];
        float4 b1 = *(const float4*)&t1[q*8+4];
        s1 = fmaf(f01.x, b0.x, s1); s1 = fmaf(f01.y, b0.y, s1);
        s1 = fmaf(f23.x, b0.z, s1); s1 = fmaf(f23.y, b0.w, s1);
        s1 = fmaf(f45.x, b1.x, s1); s1 = fmaf(f45.y, b1.y, s1);
        s1 = fmaf(f67.x, b1.z, s1); s1 = fmaf(f67.y, b1.w, s1);
        float4 g0 = *(const float4*)&t2[q*8];
        float4 g1 = *(const float4*)&t2[q*8+4];
        s2 = fmaf(f01.x, g0.x, s2); s2 = fmaf(f01.y, g0.y, s2);
        s2 = fmaf(f23.x, g0.z, s2); s2 = fmaf(f23.y, g0.w, s2);
        s2 = fmaf(f45.x, g1.x, s2); s2 = fmaf(f45.y, g1.y, s2);
        s2 = fmaf(f67.x, g1.z, s2); s2 = fmaf(f67.y, g1.w, s2);
    }
    float* op = out + (e * 16 + o) * 3;
    op[0] = s0; op[1] = s1; op[2] = s2;
}

// ---------------------------------------------------------------------------
extern "C" void kernel_launch(void* const* d_in, const int* in_sizes, int n_in,
                              void* d_out, int out_size)
{
    const float* edges = (const float*)d_in[0];
    const float* feats = (const float*)d_in[1];
    const float* basis = (const float*)d_in[2];
    const float* W1    = (const float*)d_in[3];
    const float* b1    = (const float*)d_in[4];
    const float* W2    = (const float*)d_in[5];
    const float* b2    = (const float*)d_in[6];
    const float* W3    = (const float*)d_in[7];
    float* out = (float*)d_out;

    __half *W1h, *W1l, *W2h, *W3h, *H2, *RP;
    cudaGetSymbolAddress((void**)&W1h, g_W1h);
    cudaGetSymbolAddress((void**)&W1l, g_W1l);
    cudaGetSymbolAddress((void**)&W2h, g_W2h);
    cudaGetSymbolAddress((void**)&W3h, g_W3h);
    cudaGetSymbolAddress((void**)&H2,  g_H2);
    cudaGetSymbolAddress((void**)&RP,  g_RP);

    cudaFuncSetAttribute(hgemm12,
                         cudaFuncAttributeMaxDynamicSharedMemorySize, SM12);
    cudaFuncSetAttribute(hgemm3,
                         cudaFuncAttributeMaxDynamicSharedMemorySize, SMEM_SZ);

    prep_weight<<<(256 * 32 + 255) / 256, 256>>>(W1, 32, 256, 256, 0, W1h, W1l);
    prep_weight<<<(256 * 256 + 255) / 256, 256>>>(W2, 256, 256, 256, 0, W2h, nullptr);
    prep_weight<<<(768 * 256 + 255) / 256, 256>>>(W3, 256, 768, 1536, W3OFF, W3h, nullptr);

    dim3 blk(256);
    // fused layers 1+2 -> H2 fp16
    hgemm12<<<dim3(E_TOTAL / 128, 2), blk, SM12>>>(
        edges, W1h, W1l, W2h, b1, b2, H2);
    // layer 3: H2 @ W3[:,768:1536] -> RP fp16
    hgemm3<<<dim3(E_TOTAL / 128, 6), blk, SMEM_SZ>>>(H2, W3h, RP);
    // tail
    tail_kernel<<<E_TOTAL / 16, blk>>>(RP, feats, basis, out);
}